// round 1
// baseline (speedup 1.0000x reference)
#include <cuda_runtime.h>
#include <math.h>

#define BB 2048
#define SS 512
#define HH 256
#define FF 64
#define KA (HH + FF)   // 320
#define G3 (3 * HH)    // 768

// ---------------- scratch (static device globals; no allocation) ----------------
__device__ float g_attn_in[BB * KA];   // [B, 320]
__device__ float g_logits[BB * SS];    // [B, 512]
__device__ float g_ctx[BB * HH];       // [B, 256]
__device__ float g_gi[BB * G3];        // [B, 768]
__device__ float g_gh[BB * G3];        // [B, 768]

// ---------------- kernel 0: concat(prev_hidden, y) -> attn_in ----------------
__global__ void concat_kernel(const float* __restrict__ ph,
                              const float* __restrict__ y,
                              float* __restrict__ out) {
    int i = blockIdx.x * blockDim.x + threadIdx.x;
    if (i < BB * KA) {
        int b = i / KA;
        int k = i - b * KA;
        out[i] = (k < HH) ? ph[b * HH + k] : y[b * FF + (k - HH)];
    }
}

// ---------------- tiled GEMM: C[M,N] = A[M,K] * W[N,K]^T + bias[N] ----------------
// BM=BN=64, BK=16, 256 threads, 4x4 microtile per thread.
__global__ __launch_bounds__(256)
void gemm_tn_kernel(const float* __restrict__ A,
                    const float* __restrict__ W,
                    const float* __restrict__ bias,
                    float* __restrict__ C,
                    int M, int N, int K) {
    constexpr int BM = 64, BN = 64, BK = 16;
    __shared__ __align__(16) float As[BK][BM + 4];
    __shared__ __align__(16) float Ws[BK][BN + 4];

    const int bm = blockIdx.y * BM;
    const int bn = blockIdx.x * BN;
    const int tid = threadIdx.x;
    const int tx = tid & 15;        // 0..15
    const int ty = tid >> 4;        // 0..15

    float acc[4][4];
#pragma unroll
    for (int i = 0; i < 4; i++)
#pragma unroll
        for (int j = 0; j < 4; j++) acc[i][j] = 0.0f;

    for (int k0 = 0; k0 < K; k0 += BK) {
#pragma unroll
        for (int j = 0; j < 4; j++) {
            int i = tid + 256 * j;      // 0..1023
            int r = i >> 4;             // 0..63
            int c = i & 15;             // 0..15
            As[c][r] = A[(size_t)(bm + r) * K + k0 + c];
            Ws[c][r] = W[(size_t)(bn + r) * K + k0 + c];
        }
        __syncthreads();

#pragma unroll
        for (int kk = 0; kk < BK; kk++) {
            float4 a4 = *reinterpret_cast<const float4*>(&As[kk][ty * 4]);
            float4 w4 = *reinterpret_cast<const float4*>(&Ws[kk][tx * 4]);
            float av[4] = {a4.x, a4.y, a4.z, a4.w};
            float wv[4] = {w4.x, w4.y, w4.z, w4.w};
#pragma unroll
            for (int i = 0; i < 4; i++)
#pragma unroll
                for (int j = 0; j < 4; j++) acc[i][j] += av[i] * wv[j];
        }
        __syncthreads();
    }

#pragma unroll
    for (int i = 0; i < 4; i++) {
        int m = bm + ty * 4 + i;
#pragma unroll
        for (int j = 0; j < 4; j++) {
            int n = bn + tx * 4 + j;
            float b = (bias != nullptr) ? bias[n] : 0.0f;
            C[(size_t)m * N + n] = acc[i][j] + b;
        }
    }
}

// ---------------- kernel: fused softmax over S + ctx = softmax(w) . enc ----------------
// one block per batch row, 256 threads; thread t owns hidden index t.
__global__ __launch_bounds__(256)
void softmax_ctx_kernel(const float* __restrict__ logits,
                        const float* __restrict__ enc,
                        float* __restrict__ ctx) {
    const int b = blockIdx.x;
    const int t = threadIdx.x;
    __shared__ float w[SS];
    __shared__ float red[8];

    float v0 = logits[(size_t)b * SS + t];
    float v1 = logits[(size_t)b * SS + 256 + t];

    // block max
    float mx = fmaxf(v0, v1);
#pragma unroll
    for (int o = 16; o; o >>= 1) mx = fmaxf(mx, __shfl_xor_sync(0xffffffffu, mx, o));
    if ((t & 31) == 0) red[t >> 5] = mx;
    __syncthreads();
    mx = fmaxf(fmaxf(fmaxf(red[0], red[1]), fmaxf(red[2], red[3])),
               fmaxf(fmaxf(red[4], red[5]), fmaxf(red[6], red[7])));
    __syncthreads();

    float e0 = __expf(v0 - mx);
    float e1 = __expf(v1 - mx);
    w[t] = e0;
    w[t + 256] = e1;

    // block sum
    float sm = e0 + e1;
#pragma unroll
    for (int o = 16; o; o >>= 1) sm += __shfl_xor_sync(0xffffffffu, sm, o);
    if ((t & 31) == 0) red[t >> 5] = sm;
    __syncthreads();
    float total = red[0] + red[1] + red[2] + red[3] + red[4] + red[5] + red[6] + red[7];
    float inv = 1.0f / total;

    // ctx accumulation: streams 512 * 1KB coalesced rows of enc
    const float* ep = enc + (size_t)b * SS * HH + t;
    float acc = 0.0f;
    for (int s = 0; s < SS; s += 8) {
        float ev[8];
#pragma unroll
        for (int u = 0; u < 8; u++) ev[u] = ep[(size_t)(s + u) * HH];
#pragma unroll
        for (int u = 0; u < 8; u++) acc += w[s + u] * ev[u];
    }
    ctx[(size_t)b * HH + t] = acc * inv;
}

// ---------------- kernel: GRU gates + h_new + output projection ----------------
__global__ __launch_bounds__(256)
void gru_out_kernel(const float* __restrict__ gi,
                    const float* __restrict__ gh,
                    const float* __restrict__ ph,
                    const float* __restrict__ out_W,
                    const float* __restrict__ out_b,
                    float* __restrict__ d_out) {
    const int b = blockIdx.x;
    const int t = threadIdx.x;
    __shared__ float red[8];

    const float* gib = gi + (size_t)b * G3;
    const float* ghb = gh + (size_t)b * G3;

    float ir = gib[t], iz = gib[t + 256], inn = gib[t + 512];
    float hr = ghb[t], hz = ghb[t + 256], hnn = ghb[t + 512];

    float r = 1.0f / (1.0f + expf(-(ir + hr)));
    float z = 1.0f / (1.0f + expf(-(iz + hz)));
    float n = tanhf(inn + r * hnn);
    float hp = ph[(size_t)b * HH + t];
    float h = (1.0f - z) * n + z * hp;

    // h_new goes after the [B,1] "out" block in d_out
    d_out[BB + (size_t)b * HH + t] = h;

    float p = h * out_W[t];
#pragma unroll
    for (int o = 16; o; o >>= 1) p += __shfl_xor_sync(0xffffffffu, p, o);
    if ((t & 31) == 0) red[t >> 5] = p;
    __syncthreads();
    if (t == 0) {
        float total = red[0] + red[1] + red[2] + red[3] +
                      red[4] + red[5] + red[6] + red[7];
        d_out[b] = total + out_b[0];
    }
}

// ---------------- launcher ----------------
extern "C" void kernel_launch(void* const* d_in, const int* in_sizes, int n_in,
                              void* d_out, int out_size) {
    const float* enc    = (const float*)d_in[0];   // [B,S,H]
    const float* ph     = (const float*)d_in[1];   // [B,H]
    const float* y      = (const float*)d_in[2];   // [B,F]
    const float* attn_W = (const float*)d_in[3];   // [S, H+F]
    const float* attn_b = (const float*)d_in[4];   // [S]
    const float* W_ih   = (const float*)d_in[5];   // [3H, H]
    const float* W_hh   = (const float*)d_in[6];   // [3H, H]
    const float* b_ih   = (const float*)d_in[7];   // [3H]
    const float* b_hh   = (const float*)d_in[8];   // [3H]
    const float* out_W  = (const float*)d_in[9];   // [1, H]
    const float* out_b  = (const float*)d_in[10];  // [1]
    float* out = (float*)d_out;

    float* attn_in = nullptr, *logits = nullptr, *ctx = nullptr, *gi = nullptr, *gh = nullptr;
    cudaGetSymbolAddress((void**)&attn_in, g_attn_in);
    cudaGetSymbolAddress((void**)&logits,  g_logits);
    cudaGetSymbolAddress((void**)&ctx,     g_ctx);
    cudaGetSymbolAddress((void**)&gi,      g_gi);
    cudaGetSymbolAddress((void**)&gh,      g_gh);

    // 1. concat
    {
        int total = BB * KA;
        concat_kernel<<<(total + 255) / 256, 256>>>(ph, y, attn_in);
    }
    // 2. logits GEMM: [2048,320] @ [512,320]^T + attn_b -> [2048,512]
    {
        dim3 grid(SS / 64, BB / 64);
        gemm_tn_kernel<<<grid, 256>>>(attn_in, attn_W, attn_b, logits, BB, SS, KA);
    }
    // 3. gh GEMM (independent of attention): [2048,256] @ [768,256]^T + b_hh
    {
        dim3 grid(G3 / 64, BB / 64);
        gemm_tn_kernel<<<grid, 256>>>(ph, W_hh, b_hh, gh, BB, G3, HH);
    }
    // 4. fused softmax + context
    softmax_ctx_kernel<<<BB, 256>>>(logits, enc, ctx);
    // 5. gi GEMM: [2048,256] @ [768,256]^T + b_ih
    {
        dim3 grid(G3 / 64, BB / 64);
        gemm_tn_kernel<<<grid, 256>>>(ctx, W_ih, b_ih, gi, BB, G3, HH);
    }
    // 6. gates + h_new + out projection
    gru_out_kernel<<<BB, 256>>>(gi, gh, ph, out_W, out_b, out);
}

// round 2
// speedup vs baseline: 1.0518x; 1.0518x over previous
#include <cuda_runtime.h>
#include <math.h>

#define BB 2048
#define SS 512
#define HH 256
#define FF 64
#define G3 (3 * HH)    // 768

// ---------------- scratch ----------------
__device__ float g_logits[BB * SS];    // [B, 512]
__device__ float g_ctx[BB * HH];       // [B, 256]
__device__ float g_gh[BB * G3];        // [B, 768]

// ---------------- init: d_out[0..B) = out_b ----------------
__global__ void init_out_kernel(float* __restrict__ d_out, const float* __restrict__ out_b) {
    int i = blockIdx.x * blockDim.x + threadIdx.x;
    if (i < BB) d_out[i] = out_b[0];
}

// ---------------- shared GEMM tile body ----------------
// C[M,N] = A[M,K] * W[N,K]^T + bias[N].  BM=BN=64, BK=16, 256 threads, 4x4 microtile.
// CONCAT: A row = concat(A0[256], A1[64]), K=320.
template<int KDIM, bool CONCAT>
__device__ __forceinline__ void gemm_tile(float* __restrict__ As,   // [16][68]
                                          float* __restrict__ Ws,   // [16][68]
                                          const float* __restrict__ A0,
                                          const float* __restrict__ A1,
                                          const float* __restrict__ W,
                                          const float* __restrict__ bias,
                                          float* __restrict__ C, int N) {
    const int bm = blockIdx.y * 64;
    const int bn = blockIdx.x * 64;
    const int tid = threadIdx.x;
    const int tx = tid & 15;
    const int ty = tid >> 4;

    float acc[4][4];
#pragma unroll
    for (int i = 0; i < 4; i++)
#pragma unroll
        for (int j = 0; j < 4; j++) acc[i][j] = 0.0f;

    for (int k0 = 0; k0 < KDIM; k0 += 16) {
#pragma unroll
        for (int j = 0; j < 4; j++) {
            int i = tid + 256 * j;
            int r = i >> 4;
            int c = i & 15;
            int k = k0 + c;
            float a;
            if (CONCAT)
                a = (k < 256) ? A0[(size_t)(bm + r) * 256 + k]
                              : A1[(size_t)(bm + r) * 64 + (k - 256)];
            else
                a = A0[(size_t)(bm + r) * KDIM + k];
            As[c * 68 + r] = a;
            Ws[c * 68 + r] = W[(size_t)(bn + r) * KDIM + k];
        }
        __syncthreads();

#pragma unroll
        for (int kk = 0; kk < 16; kk++) {
            float4 a4 = *reinterpret_cast<const float4*>(&As[kk * 68 + ty * 4]);
            float4 w4 = *reinterpret_cast<const float4*>(&Ws[kk * 68 + tx * 4]);
            float av[4] = {a4.x, a4.y, a4.z, a4.w};
            float wv[4] = {w4.x, w4.y, w4.z, w4.w};
#pragma unroll
            for (int i = 0; i < 4; i++)
#pragma unroll
                for (int j = 0; j < 4; j++) acc[i][j] = fmaf(av[i], wv[j], acc[i][j]);
        }
        __syncthreads();
    }

#pragma unroll
    for (int i = 0; i < 4; i++) {
        int m = bm + ty * 4 + i;
#pragma unroll
        for (int j = 0; j < 4; j++) {
            int n = bn + tx * 4 + j;
            C[(size_t)m * N + n] = acc[i][j] + bias[n];
        }
    }
}

// ---------------- K1: combined logits GEMM (with fused concat) + gh GEMM ----------------
// grid(12, 32, 2). z=0: logits (x<8 only), z=1: gh.
__global__ __launch_bounds__(256)
void k1_gemms(const float* __restrict__ ph, const float* __restrict__ y,
              const float* __restrict__ attn_W, const float* __restrict__ attn_b,
              const float* __restrict__ W_hh, const float* __restrict__ b_hh,
              float* __restrict__ logits, float* __restrict__ gh) {
    __shared__ __align__(16) float As[16 * 68];
    __shared__ __align__(16) float Ws[16 * 68];
    if (blockIdx.z == 0) {
        if (blockIdx.x >= 8) return;
        gemm_tile<320, true>(As, Ws, ph, y, attn_W, attn_b, logits, SS);
    } else {
        gemm_tile<256, false>(As, Ws, ph, nullptr, W_hh, b_hh, gh, G3);
    }
}

// ---------------- K2: fused softmax + ctx (float4 streaming) ----------------
__global__ __launch_bounds__(256)
void softmax_ctx_kernel(const float* __restrict__ logits,
                        const float* __restrict__ enc,
                        float* __restrict__ ctx) {
    const int b = blockIdx.x;
    const int t = threadIdx.x;
    __shared__ float w[SS];
    __shared__ float red[8];
    __shared__ __align__(16) float4 part[256];

    float v0 = logits[(size_t)b * SS + t];
    float v1 = logits[(size_t)b * SS + 256 + t];

    float mx = fmaxf(v0, v1);
#pragma unroll
    for (int o = 16; o; o >>= 1) mx = fmaxf(mx, __shfl_xor_sync(0xffffffffu, mx, o));
    if ((t & 31) == 0) red[t >> 5] = mx;
    __syncthreads();
    mx = fmaxf(fmaxf(fmaxf(red[0], red[1]), fmaxf(red[2], red[3])),
               fmaxf(fmaxf(red[4], red[5]), fmaxf(red[6], red[7])));
    __syncthreads();

    float e0 = __expf(v0 - mx);
    float e1 = __expf(v1 - mx);
    w[t] = e0;
    w[t + 256] = e1;

    float sm = e0 + e1;
#pragma unroll
    for (int o = 16; o; o >>= 1) sm += __shfl_xor_sync(0xffffffffu, sm, o);
    if ((t & 31) == 0) red[t >> 5] = sm;
    __syncthreads();
    float inv = 1.0f / (red[0] + red[1] + red[2] + red[3] +
                        red[4] + red[5] + red[6] + red[7]);

    // ctx: stream 512KB of enc per block via float4, evict-first
    const float4* ep = reinterpret_cast<const float4*>(enc + (size_t)b * SS * HH);
    const int hq = t & 63;   // float4 index within a 256-float row
    const int sr = t >> 6;   // 0..3: sub-row within a group of 4 rows
    float4 acc = make_float4(0.f, 0.f, 0.f, 0.f);

    for (int s0 = 0; s0 < SS; s0 += 32) {
#pragma unroll
        for (int u = 0; u < 8; u++) {
            int row = s0 + u * 4 + sr;
            float4 v = __ldcs(&ep[(size_t)row * 64 + hq]);
            float ww = w[row];
            acc.x = fmaf(ww, v.x, acc.x);
            acc.y = fmaf(ww, v.y, acc.y);
            acc.z = fmaf(ww, v.z, acc.z);
            acc.w = fmaf(ww, v.w, acc.w);
        }
    }

    part[t] = acc;
    __syncthreads();
    if (t < 64) {
        float4 a = part[t], b4 = part[t + 64], c4 = part[t + 128], d4 = part[t + 192];
        float4 r;
        r.x = (a.x + b4.x + c4.x + d4.x) * inv;
        r.y = (a.y + b4.y + c4.y + d4.y) * inv;
        r.z = (a.z + b4.z + c4.z + d4.z) * inv;
        r.w = (a.w + b4.w + c4.w + d4.w) * inv;
        *reinterpret_cast<float4*>(&ctx[(size_t)b * HH + t * 4]) = r;
    }
}

// ---------------- K3: gi GEMM (all 3 gates per tile) + GRU gates + h_new + out ----------------
// grid(4, 32): x = hidden tile (64 of 256), y = batch tile (64 of 2048).
__global__ __launch_bounds__(256)
void k3_gru_kernel(const float* __restrict__ ctx,
                   const float* __restrict__ W_ih, const float* __restrict__ b_ih,
                   const float* __restrict__ gh,  const float* __restrict__ ph,
                   const float* __restrict__ outW, float* __restrict__ d_out) {
    __shared__ __align__(16) float As[16 * 68];        // ctx tile [k][b]
    __shared__ __align__(16) float Ws[3][16 * 68];     // W_ih tiles per gate [k][h]

    const int bm = blockIdx.y * 64;   // batch base
    const int bh = blockIdx.x * 64;   // hidden base
    const int tid = threadIdx.x;
    const int tx = tid & 15;
    const int ty = tid >> 4;

    float acc[4][4][3];
#pragma unroll
    for (int i = 0; i < 4; i++)
#pragma unroll
        for (int j = 0; j < 4; j++)
#pragma unroll
            for (int g = 0; g < 3; g++) acc[i][j][g] = 0.0f;

    for (int k0 = 0; k0 < HH; k0 += 16) {
#pragma unroll
        for (int j = 0; j < 4; j++) {
            int i = tid + 256 * j;
            int r = i >> 4, c = i & 15;
            As[c * 68 + r] = ctx[(size_t)(bm + r) * HH + k0 + c];
        }
#pragma unroll
        for (int j = 0; j < 12; j++) {
            int i = tid + 256 * j;          // 0..3071
            int r = i >> 4, c = i & 15;     // r: 0..191
            int g = r >> 6, rr = r & 63;
            Ws[g][c * 68 + rr] = W_ih[(size_t)(g * HH + bh + rr) * HH + k0 + c];
        }
        __syncthreads();

#pragma unroll
        for (int kk = 0; kk < 16; kk++) {
            float4 a4 = *reinterpret_cast<const float4*>(&As[kk * 68 + ty * 4]);
            float av[4] = {a4.x, a4.y, a4.z, a4.w};
#pragma unroll
            for (int g = 0; g < 3; g++) {
                float4 w4 = *reinterpret_cast<const float4*>(&Ws[g][kk * 68 + tx * 4]);
                float wv[4] = {w4.x, w4.y, w4.z, w4.w};
#pragma unroll
                for (int i = 0; i < 4; i++)
#pragma unroll
                    for (int j = 0; j < 4; j++)
                        acc[i][j][g] = fmaf(av[i], wv[j], acc[i][j][g]);
            }
        }
        __syncthreads();
    }

    // epilogue: gates, h_new, out projection
#pragma unroll
    for (int i = 0; i < 4; i++) {
        const int b = bm + ty * 4 + i;
        const float* ghb = gh + (size_t)b * G3;
        float p = 0.0f;
#pragma unroll
        for (int j = 0; j < 4; j++) {
            const int h = bh + tx * 4 + j;
            float gir = acc[i][j][0] + b_ih[h];
            float giz = acc[i][j][1] + b_ih[h + 256];
            float gin = acc[i][j][2] + b_ih[h + 512];
            float r = 1.0f / (1.0f + __expf(-(gir + ghb[h])));
            float z = 1.0f / (1.0f + __expf(-(giz + ghb[h + 256])));
            float n = tanhf(gin + r * ghb[h + 512]);
            float hv = (1.0f - z) * n + z * ph[(size_t)b * HH + h];
            d_out[BB + (size_t)b * HH + h] = hv;
            p = fmaf(hv, outW[h], p);
        }
        // reduce p across the 16 lanes sharing this batch row
        p += __shfl_xor_sync(0xffffffffu, p, 1);
        p += __shfl_xor_sync(0xffffffffu, p, 2);
        p += __shfl_xor_sync(0xffffffffu, p, 4);
        p += __shfl_xor_sync(0xffffffffu, p, 8);
        if (tx == 0) atomicAdd(&d_out[b], p);
    }
}

// ---------------- launcher ----------------
extern "C" void kernel_launch(void* const* d_in, const int* in_sizes, int n_in,
                              void* d_out, int out_size) {
    const float* enc    = (const float*)d_in[0];
    const float* ph     = (const float*)d_in[1];
    const float* y      = (const float*)d_in[2];
    const float* attn_W = (const float*)d_in[3];
    const float* attn_b = (const float*)d_in[4];
    const float* W_ih   = (const float*)d_in[5];
    const float* W_hh   = (const float*)d_in[6];
    const float* b_ih   = (const float*)d_in[7];
    const float* b_hh   = (const float*)d_in[8];
    const float* out_W  = (const float*)d_in[9];
    const float* out_b  = (const float*)d_in[10];
    float* out = (float*)d_out;

    float *logits = nullptr, *ctx = nullptr, *gh = nullptr;
    cudaGetSymbolAddress((void**)&logits, g_logits);
    cudaGetSymbolAddress((void**)&ctx,    g_ctx);
    cudaGetSymbolAddress((void**)&gh,     g_gh);

    init_out_kernel<<<(BB + 255) / 256, 256>>>(out, out_b);

    {
        dim3 grid(12, 32, 2);
        k1_gemms<<<grid, 256>>>(ph, y, attn_W, attn_b, W_hh, b_hh, logits, gh);
    }

    softmax_ctx_kernel<<<BB, 256>>>(logits, enc, ctx);

    {
        dim3 grid(4, 32);
        k3_gru_kernel<<<grid, 256>>>(ctx, W_ih, b_ih, gh, ph, out_W, out);
    }
}